// round 15
// baseline (speedup 1.0000x reference)
#include <cuda_runtime.h>
#include <cuda_fp16.h>
#include <math.h>
#include <stdint.h>

#define D_MODEL 1024
#define SEQ     2048
#define BATCH   4
#define NHEADS  16
#define HDIM    64
#define M_TOTAL (BATCH * SEQ)      // 8192
#define LN_EPS  1e-5f

// ---------------------------------------------------------------------------
// Scratch buffers (allocation-free rule: __device__ globals)
// ---------------------------------------------------------------------------
__device__ float  g_x1 [M_TOTAL * D_MODEL];
__device__ __half g_a  [M_TOTAL * D_MODEL];
__device__ __half g_q  [M_TOTAL * D_MODEL];
__device__ __half g_k  [M_TOTAL * D_MODEL];
__device__ __half g_v  [M_TOTAL * D_MODEL];
__device__ __half g_h1 [M_TOTAL * D_MODEL];
__device__ __half g_wh [6 * D_MODEL * D_MODEL];

// ---------------------------------------------------------------------------
// Helpers (sm_80+ ISA: mma.sync / ldmatrix / cp.async)
// ---------------------------------------------------------------------------
__device__ __forceinline__ uint32_t smem_u32(const void* p) {
    uint32_t a;
    asm("{ .reg .u64 t; cvta.to.shared.u64 t, %1; cvt.u32.u64 %0, t; }" : "=r"(a) : "l"(p));
    return a;
}
#define CP_ASYNC16(sa, g) \
    asm volatile("cp.async.cg.shared.global [%0], [%1], 16;" :: "r"(sa), "l"(g) : "memory")
#define CP_COMMIT() asm volatile("cp.async.commit_group;" ::: "memory")
#define CP_WAIT0()  asm volatile("cp.async.wait_group 0;" ::: "memory")
#define CP_WAIT1()  asm volatile("cp.async.wait_group 1;" ::: "memory")

__device__ __forceinline__ void ldsm4(uint32_t* r, uint32_t addr) {
    asm volatile("ldmatrix.sync.aligned.m8n8.x4.shared.b16 {%0,%1,%2,%3}, [%4];"
                 : "=r"(r[0]), "=r"(r[1]), "=r"(r[2]), "=r"(r[3]) : "r"(addr));
}
__device__ __forceinline__ void ldsm4t(uint32_t* r, uint32_t addr) {
    asm volatile("ldmatrix.sync.aligned.m8n8.x4.trans.shared.b16 {%0,%1,%2,%3}, [%4];"
                 : "=r"(r[0]), "=r"(r[1]), "=r"(r[2]), "=r"(r[3]) : "r"(addr));
}
// f32-accumulator HMMA
__device__ __forceinline__ void mma_f16(float* d, const uint32_t* a, const uint32_t* b) {
    asm volatile("mma.sync.aligned.m16n8k16.row.col.f32.f16.f16.f32 "
                 "{%0,%1,%2,%3}, {%4,%5,%6,%7}, {%8,%9}, {%0,%1,%2,%3};"
                 : "+f"(d[0]), "+f"(d[1]), "+f"(d[2]), "+f"(d[3])
                 : "r"(a[0]), "r"(a[1]), "r"(a[2]), "r"(a[3]), "r"(b[0]), "r"(b[1]));
}
// f16-accumulator HMMA (2x rate): d0={row r, 2 cols}, d1={row r+8, 2 cols}
__device__ __forceinline__ void mma_f16h(uint32_t* d, const uint32_t* a, const uint32_t* b) {
    asm volatile("mma.sync.aligned.m16n8k16.row.col.f16.f16.f16.f16 "
                 "{%0,%1}, {%2,%3,%4,%5}, {%6,%7}, {%0,%1};"
                 : "+r"(d[0]), "+r"(d[1])
                 : "r"(a[0]), "r"(a[1]), "r"(a[2]), "r"(a[3]), "r"(b[0]), "r"(b[1]));
}
#define EX2(d, x) asm("ex2.approx.ftz.f32 %0, %1;" : "=f"(d) : "f"(x))

__device__ __forceinline__ uint32_t packh2(float v0, float v1) {
    __half2 t = __floats2half2_rn(v0, v1);
    return *(uint32_t*)&t;
}
__device__ __forceinline__ uint32_t maxh2(uint32_t a, uint32_t b) {
    uint32_t d;
    asm("max.f16x2 %0, %1, %2;" : "=r"(d) : "r"(a), "r"(b));
    return d;
}
__device__ __forceinline__ uint32_t hfma2r(uint32_t a, uint32_t b, uint32_t c) {
    uint32_t d;
    asm("fma.rn.f16x2 %0, %1, %2, %3;" : "=r"(d) : "r"(a), "r"(b), "r"(c));
    return d;
}
__device__ __forceinline__ uint32_t ex2h2(uint32_t a) {
    uint32_t d;
    asm("ex2.approx.f16x2 %0, %1;" : "=r"(d) : "r"(a));
    return d;
}

// ---------------------------------------------------------------------------
// All six weight conversions (fp32 -> fp16) in one launch
// ---------------------------------------------------------------------------
__global__ void __launch_bounds__(256) wconv6_kernel(
    const float* __restrict__ w0, const float* __restrict__ w1,
    const float* __restrict__ w2, const float* __restrict__ w3,
    const float* __restrict__ w4, const float* __restrict__ w5,
    __half* __restrict__ dst)
{
    const int ws = blockIdx.y;
    const float* src = (ws == 0) ? w0 : (ws == 1) ? w1 : (ws == 2) ? w2
                     : (ws == 3) ? w3 : (ws == 4) ? w4 : w5;
    const int i = blockIdx.x * 256 + threadIdx.x;
    const float4 v = ((const float4*)src)[i];
    const size_t base = (size_t)ws * (D_MODEL * D_MODEL / 2) + 2 * i;
    ((uint32_t*)dst)[base]     = packh2(v.x, v.y);
    ((uint32_t*)dst)[base + 1] = packh2(v.z, v.w);
}

// ---------------------------------------------------------------------------
// Fused LayerNorm -> single fp16
// ---------------------------------------------------------------------------
__global__ void __launch_bounds__(256) ln_half_kernel(
    const float* __restrict__ x, const float* __restrict__ g,
    const float* __restrict__ b, __half* __restrict__ y)
{
    __shared__ float red[16];
    const int row = blockIdx.x;
    const int tid = threadIdx.x;
    const float4 v = ((const float4*)(x + (size_t)row * D_MODEL))[tid];

    float s  = v.x + v.y + v.z + v.w;
    float ss = v.x * v.x + v.y * v.y + v.z * v.z + v.w * v.w;
    #pragma unroll
    for (int o = 16; o; o >>= 1) {
        s  += __shfl_xor_sync(0xffffffffu, s,  o);
        ss += __shfl_xor_sync(0xffffffffu, ss, o);
    }
    const int wid = tid >> 5;
    if ((tid & 31) == 0) { red[wid] = s; red[8 + wid] = ss; }
    __syncthreads();
    float S = 0.f, SS = 0.f;
    #pragma unroll
    for (int w = 0; w < 8; w++) { S += red[w]; SS += red[8 + w]; }
    const float mu   = S * (1.0f / D_MODEL);
    const float var  = SS * (1.0f / D_MODEL) - mu * mu;
    const float rstd = rsqrtf(var + LN_EPS);

    const float4 gv = ((const float4*)g)[tid];
    const float4 bv = ((const float4*)b)[tid];
    const float o0 = (v.x - mu) * rstd * gv.x + bv.x;
    const float o1 = (v.y - mu) * rstd * gv.y + bv.y;
    const float o2 = (v.z - mu) * rstd * gv.z + bv.z;
    const float o3 = (v.w - mu) * rstd * gv.w + bv.w;
    const size_t base = (size_t)row * (D_MODEL / 2) + tid * 2;
    ((uint32_t*)y)[base]     = packh2(o0, o1);
    ((uint32_t*)y)[base + 1] = packh2(o2, o3);
}

// ---------------------------------------------------------------------------
// fp16 GEMM (R10 shape: 8 warps, 64x32 warp tiles, 2-stage — pinned best)
// ---------------------------------------------------------------------------
#define TILE_B   16384
#define STAGE_B  (2 * TILE_B)           // A, W = 32KB
#define MMG_SMEM (2 * STAGE_B)          // 65536

__device__ __forceinline__ uint32_t swadr(uint32_t tbase, int row, int chunk) {
    return tbase + row * 128 + (((chunk ^ row) & 7) << 4) + ((chunk & ~7) << 4);
}

__global__ void __launch_bounds__(256, 2)
mm_gemm(const __half* __restrict__ A, const __half* __restrict__ W,
        const float* __restrict__ bias0, const float* __restrict__ bias1,
        const float* __restrict__ bias2, const float* __restrict__ res,
        float* __restrict__ Cf, __half* __restrict__ C0,
        __half* __restrict__ C1, __half* __restrict__ C2, int doRelu)
{
    extern __shared__ char smem[];
    const uint32_t sb = smem_u32(smem);
    const int tid = threadIdx.x;
    const int wid = tid >> 5;
    const int lid = tid & 31;
    const int warpM = wid >> 2;
    const int warpN = wid & 3;
    const int grp = blockIdx.x >> 3;
    const int cn  = (blockIdx.x & 7) * 128;
    const int bm  = blockIdx.y * 128;

    const float* bias = (grp == 0) ? bias0 : (grp == 1) ? bias1 : bias2;
    __half* Ch = (grp == 0) ? C0 : (grp == 1) ? C1 : C2;

    const __half* baseA = A + (size_t)bm * 1024;
    const __half* baseW = W + (size_t)blockIdx.x * 128 * 1024;

    #define LOAD_CHUNK(stg, k0) do {                                              \
        const uint32_t _sbase = sb + (stg) * STAGE_B;                             \
        _Pragma("unroll")                                                         \
        for (int i = 0; i < 8; i++) {                                             \
            const int tile = i >> 2;                                              \
            const int idx  = (tid + i * 256) & 1023;                              \
            const int r    = idx >> 3;                                            \
            const int c8   = idx & 7;                                             \
            const __half* gp = (tile == 0 ? baseA : baseW)                        \
                + (size_t)r * 1024 + (k0) + c8 * 8;                               \
            const uint32_t sa = _sbase + tile * TILE_B +                          \
                (uint32_t)(r * 128 + (((c8 ^ r) & 7) << 4));                      \
            CP_ASYNC16(sa, gp);                                                   \
        }                                                                         \
        CP_COMMIT();                                                              \
    } while (0)

    float acc[4][4][4];
    #pragma unroll
    for (int a = 0; a < 4; a++)
        #pragma unroll
        for (int b = 0; b < 4; b++)
            #pragma unroll
            for (int c = 0; c < 4; c++) acc[a][b][c] = 0.f;

    const int aRow = warpM * 64 + (lid & 15);
    const int aChk = lid >> 4;
    const int bRow = warpN * 32 + ((lid >= 16) ? 8 : 0) + (lid & 7);
    const int bChk = (lid >> 3) & 1;

    LOAD_CHUNK(0, 0);

    #pragma unroll 1
    for (int c = 0; c < 16; c++) {
        const int s = c & 1;
        __syncthreads();
        if (c < 15) { LOAD_CHUNK(s ^ 1, (c + 1) * 64); CP_WAIT1(); }
        else        { CP_WAIT0(); }
        __syncthreads();

        const uint32_t sA = sb + s * STAGE_B;
        const uint32_t sW = sA + TILE_B;

        #pragma unroll
        for (int s16 = 0; s16 < 4; s16++) {
            const int kc = s16 * 2;
            uint32_t Bf[4][2];
            #pragma unroll
            for (int pair = 0; pair < 2; pair++)
                ldsm4(&Bf[pair * 2][0], swadr(sW, bRow + pair * 16, kc + bChk));
            #pragma unroll
            for (int mt = 0; mt < 4; mt++) {
                uint32_t Af[4];
                ldsm4(Af, swadr(sA, aRow + mt * 16, kc + aChk));
                #pragma unroll
                for (int nt = 0; nt < 4; nt++)
                    mma_f16(acc[mt][nt], Af, Bf[nt]);
            }
        }
    }

    const int rowoff = lid >> 2;
    const int coloff = (lid & 3) * 2;
    #pragma unroll
    for (int mt = 0; mt < 4; mt++) {
        #pragma unroll
        for (int nt = 0; nt < 4; nt++) {
            const int gn = cn + warpN * 32 + nt * 8 + coloff;
            const float b0 = __ldg(&bias[gn]);
            const float b1 = __ldg(&bias[gn + 1]);
            #pragma unroll
            for (int half = 0; half < 2; half++) {
                const int gm = bm + warpM * 64 + mt * 16 + rowoff + half * 8;
                float v0 = acc[mt][nt][half * 2 + 0] + b0;
                float v1 = acc[mt][nt][half * 2 + 1] + b1;
                if (doRelu) { v0 = fmaxf(v0, 0.f); v1 = fmaxf(v1, 0.f); }
                const size_t off = (size_t)gm * 1024 + gn;
                if (res) {
                    const float2 rv = *(const float2*)&res[off];
                    v0 += rv.x; v1 += rv.y;
                }
                if (Cf) *(float2*)&Cf[off] = make_float2(v0, v1);
                else    *(uint32_t*)&Ch[off] = packh2(v0, v1);
            }
        }
    }
}

// ---------------------------------------------------------------------------
// Flash attention v5: fp16 softmax path (R14) + PV with f16 accumulators.
// Per tile: PV accumulates in fp16 HMMA (2x rate), promoted to persistent
// f32 o once per tile. l stays on the f32 ones-MMA (scale is exact).
// Tensor units/tile-pair: 208 -> 144.
// ---------------------------------------------------------------------------
#define AQ 128
#define AK 64
#define ATT_ST   16384
#define ATT_STB  16384
#define ATT_SMEM (ATT_ST + 3 * ATT_STB)   // 65536

// One row-tile softmax: scores in sch[8][2] (packed), in-place -> probs.
__device__ __forceinline__ void softmax_h(
    uint32_t sch[8][2], float& m0, float& m1, float o[8][4], float lacc[4],
    float csf, uint32_t cs2)
{
    uint32_t t0 = sch[0][0], t1 = sch[0][1];
    #pragma unroll
    for (int j = 1; j < 8; j++) { t0 = maxh2(t0, sch[j][0]); t1 = maxh2(t1, sch[j][1]); }
    uint32_t pm = maxh2(__byte_perm(t0, t1, 0x5410), __byte_perm(t0, t1, 0x7632));
    #pragma unroll
    for (int d = 1; d < 4; d <<= 1)
        pm = maxh2(pm, __shfl_xor_sync(0xffffffffu, pm, d));
    const __half2 pmh = *(const __half2*)&pm;
    const float mx0 = __low2float(pmh)  * csf;
    const float mx1 = __high2float(pmh) * csf;
    const float m0n = fmaxf(m0, mx0);
    const float m1n = fmaxf(m1, mx1);
    float s0, s1;
    EX2(s0, m0 - m0n);
    EX2(s1, m1 - m1n);
    m0 = m0n; m1 = m1n;

    const uint32_t nm0 = packh2(-m0n, -m0n);
    const uint32_t nm1 = packh2(-m1n, -m1n);
    #pragma unroll
    for (int j = 0; j < 8; j++) {
        sch[j][0] = ex2h2(hfma2r(sch[j][0], cs2, nm0));
        sch[j][1] = ex2h2(hfma2r(sch[j][1], cs2, nm1));
    }
    #pragma unroll
    for (int j = 0; j < 8; j++) {
        o[j][0] *= s0; o[j][1] *= s0;
        o[j][2] *= s1; o[j][3] *= s1;
    }
    lacc[0] *= s0; lacc[1] *= s0;
    lacc[2] *= s1; lacc[3] *= s1;
}

__global__ void __launch_bounds__(128, 2) attn_mma(
    const __half* __restrict__ Q, const __half* __restrict__ K,
    const __half* __restrict__ V, __half* __restrict__ O)
{
    extern __shared__ char smem[];
    const uint32_t sb = smem_u32(smem);
    const int tid = threadIdx.x;
    const int wid = tid >> 5;
    const int lid = tid & 31;
    const int bh  = blockIdx.y;
    const int b   = bh >> 4;
    const int h   = bh & 15;
    const int q0  = blockIdx.x * AQ;
    const size_t rowBase = (size_t)b * SEQ;
    const int hcol = h * HDIM;

    {
        #pragma unroll
        for (int i = 0; i < 8; i++) {
            const int idx = tid + i * 128;
            const int r   = idx >> 3;
            const int c8  = idx & 7;
            const __half* gp = Q + (rowBase + q0 + r) * 1024 + hcol + c8 * 8;
            const uint32_t sa = sb + (uint32_t)(r * 128 + (((c8 ^ r) & 7) << 4));
            CP_ASYNC16(sa, gp);
        }
        CP_COMMIT();
    }

    #define LOAD_KV(stg, kt) do {                                               \
        const uint32_t _sbase = sb + ATT_ST + (stg) * ATT_STB;                  \
        _Pragma("unroll")                                                       \
        for (int i = 0; i < 8; i++) {                                           \
            const int tile = i >> 2;                                            \
            const int idx  = (tid + (i & 3) * 128) & 511;                       \
            const int r    = idx >> 3;                                          \
            const int c8   = idx & 7;                                           \
            const __half* gp = (tile ? V : K)                                   \
                + (rowBase + (kt) * AK + r) * 1024 + hcol + c8 * 8;             \
            const uint32_t sa = _sbase + tile * 8192 +                          \
                (uint32_t)(r * 128 + (((c8 ^ r) & 7) << 4));                    \
            CP_ASYNC16(sa, gp);                                                 \
        }                                                                       \
        CP_COMMIT();                                                            \
    } while (0)

    LOAD_KV(0, 0);
    LOAD_KV(1, 1);
    CP_WAIT1();
    __syncthreads();

    uint32_t Qf0[4][4], Qf1[4][4];
    {
        const int r0 = wid * 32 + (lid & 15);
        const int ck = lid >> 4;
        #pragma unroll
        for (int t = 0; t < 4; t++) {
            ldsm4(Qf0[t], swadr(sb, r0,      2 * t + ck));
            ldsm4(Qf1[t], swadr(sb, r0 + 16, 2 * t + ck));
        }
    }

    float o0[8][4], o1[8][4], lacc0[4], lacc1[4];
    #pragma unroll
    for (int j = 0; j < 8; j++)
        #pragma unroll
        for (int e = 0; e < 4; e++) { o0[j][e] = 0.f; o1[j][e] = 0.f; }
    #pragma unroll
    for (int e = 0; e < 4; e++) { lacc0[e] = 0.f; lacc1[e] = 0.f; }
    float m00 = -INFINITY, m01 = -INFINITY, m10 = -INFINITY, m11 = -INFINITY;

    const float csf = __half2float(__float2half_rn(0.125f * 1.4426950408889634f));
    const uint32_t cs2 = packh2(csf, csf);
    const uint32_t onesb[2] = { 0x3C003C00u, 0x3C003C00u };   // packed 1.0h

    const int kRowL = ((lid >= 16) ? 8 : 0) + (lid & 7);
    const int kChkL = (lid >> 3) & 1;
    const int vT    = lid >> 3;
    const int vKeyL = ((vT & 1) << 3) + (lid & 7);
    const int vChkL = vT >> 1;

    #pragma unroll 1
    for (int kt = 0; kt < SEQ / AK; kt++) {
        if (kt > 0) {
            if (kt == SEQ / AK - 1) CP_WAIT0(); else CP_WAIT1();
            __syncthreads();
        }
        if (kt + 2 < SEQ / AK) LOAD_KV((kt + 2) % 3, kt + 2);

        const uint32_t sK = sb + ATT_ST + (kt % 3) * ATT_STB;
        const uint32_t sV = sK + 8192;

        // ---- S = Q K^T, f16 accumulators ----
        uint32_t sch0[8][2], sch1[8][2];
        #pragma unroll
        for (int j = 0; j < 8; j++) {
            sch0[j][0] = 0u; sch0[j][1] = 0u;
            sch1[j][0] = 0u; sch1[j][1] = 0u;
        }

        #pragma unroll
        for (int t = 0; t < 4; t++) {
            #pragma unroll
            for (int kp = 0; kp < 4; kp++) {
                uint32_t kf[4];
                ldsm4(kf, swadr(sK, kp * 16 + kRowL, 2 * t + kChkL));
                mma_f16h(sch0[2 * kp],     Qf0[t], kf);
                mma_f16h(sch0[2 * kp + 1], Qf0[t], kf + 2);
                mma_f16h(sch1[2 * kp],     Qf1[t], kf);
                mma_f16h(sch1[2 * kp + 1], Qf1[t], kf + 2);
            }
        }

        // ---- packed softmax (in-place: sch -> probs) ----
        softmax_h(sch0, m00, m01, o0, lacc0, csf, cs2);
        softmax_h(sch1, m10, m11, o1, lacc1, csf, cs2);

        // ---- tile PV in f16 accumulators; l via f32 ones-MMA ----
        uint32_t oh0[8][2], oh1[8][2];
        #pragma unroll
        for (int jn = 0; jn < 8; jn++) {
            oh0[jn][0] = 0u; oh0[jn][1] = 0u;
            oh1[jn][0] = 0u; oh1[jn][1] = 0u;
        }
        #pragma unroll
        for (int kb = 0; kb < 4; kb++) {
            const uint32_t pa0[4] = { sch0[2 * kb][0], sch0[2 * kb][1],
                                      sch0[2 * kb + 1][0], sch0[2 * kb + 1][1] };
            const uint32_t pa1[4] = { sch1[2 * kb][0], sch1[2 * kb][1],
                                      sch1[2 * kb + 1][0], sch1[2 * kb + 1][1] };
            mma_f16(lacc0, pa0, onesb);
            mma_f16(lacc1, pa1, onesb);
            #pragma unroll
            for (int np = 0; np < 4; np++) {
                uint32_t vf[4];
                ldsm4t(vf, swadr(sV, kb * 16 + vKeyL, np * 2 + vChkL));
                mma_f16h(oh0[2 * np],     pa0, vf);
                mma_f16h(oh0[2 * np + 1], pa0, vf + 2);
                mma_f16h(oh1[2 * np],     pa1, vf);
                mma_f16h(oh1[2 * np + 1], pa1, vf + 2);
            }
        }
        // ---- promote tile sums into persistent f32 o ----
        #pragma unroll
        for (int jn = 0; jn < 8; jn++) {
            const float2 a0 = __half22float2(*(const __half2*)&oh0[jn][0]);
            const float2 b0 = __half22float2(*(const __half2*)&oh0[jn][1]);
            o0[jn][0] += a0.x; o0[jn][1] += a0.y;
            o0[jn][2] += b0.x; o0[jn][3] += b0.y;
            const float2 a1 = __half22float2(*(const __half2*)&oh1[jn][0]);
            const float2 b1 = __half22float2(*(const __half2*)&oh1[jn][1]);
            o1[jn][0] += a1.x; o1[jn][1] += a1.y;
            o1[jn][2] += b1.x; o1[jn][3] += b1.y;
        }
    }

    // ---- epilogue: l comes straight from the ones-MMA (no shuffles) ----
    const int cb = hcol + (lid & 3) * 2;
    {
        const float il0 = 1.0f / lacc0[0];
        const float il1 = 1.0f / lacc0[2];
        const size_t row0 = rowBase + q0 + wid * 32 + (lid >> 2);
        const size_t row1 = row0 + 8;
        #pragma unroll
        for (int j = 0; j < 8; j++) {
            const int col = cb + j * 8;
            *(uint32_t*)&O[row0 * 1024 + col] = packh2(o0[j][0] * il0, o0[j][1] * il0);
            *(uint32_t*)&O[row1 * 1024 + col] = packh2(o0[j][2] * il1, o0[j][3] * il1);
        }
    }
    {
        const float il0 = 1.0f / lacc1[0];
        const float il1 = 1.0f / lacc1[2];
        const size_t row0 = rowBase + q0 + wid * 32 + 16 + (lid >> 2);
        const size_t row1 = row0 + 8;
        #pragma unroll
        for (int j = 0; j < 8; j++) {
            const int col = cb + j * 8;
            *(uint32_t*)&O[row0 * 1024 + col] = packh2(o1[j][0] * il0, o1[j][1] * il0);
            *(uint32_t*)&O[row1 * 1024 + col] = packh2(o1[j][2] * il1, o1[j][3] * il1);
        }
    }
}

// ---------------------------------------------------------------------------
// Launch
// ---------------------------------------------------------------------------
extern "C" void kernel_launch(void* const* d_in, const int* in_sizes, int n_in,
                              void* d_out, int out_size)
{
    const float* src = (const float*)d_in[0];
    const float* Wq  = (const float*)d_in[1];  const float* bq = (const float*)d_in[2];
    const float* Wk  = (const float*)d_in[3];  const float* bk = (const float*)d_in[4];
    const float* Wv  = (const float*)d_in[5];  const float* bv = (const float*)d_in[6];
    const float* Wo  = (const float*)d_in[7];  const float* bo = (const float*)d_in[8];
    const float* W1  = (const float*)d_in[9];  const float* b1 = (const float*)d_in[10];
    const float* W2  = (const float*)d_in[11]; const float* b2 = (const float*)d_in[12];
    const float* g1  = (const float*)d_in[13]; const float* be1 = (const float*)d_in[14];
    const float* g2  = (const float*)d_in[15]; const float* be2 = (const float*)d_in[16];
    float* out = (float*)d_out;

    float* x1;
    __half *a, *q, *k, *v, *h1, *wh;
    cudaGetSymbolAddress((void**)&x1, g_x1);
    cudaGetSymbolAddress((void**)&a,  g_a);
    cudaGetSymbolAddress((void**)&q,  g_q);
    cudaGetSymbolAddress((void**)&k,  g_k);
    cudaGetSymbolAddress((void**)&v,  g_v);
    cudaGetSymbolAddress((void**)&h1, g_h1);
    cudaGetSymbolAddress((void**)&wh, g_wh);

    cudaFuncSetAttribute(mm_gemm,  cudaFuncAttributeMaxDynamicSharedMemorySize, MMG_SMEM);
    cudaFuncSetAttribute(attn_mma, cudaFuncAttributeMaxDynamicSharedMemorySize, ATT_SMEM);

    const int WN = D_MODEL * D_MODEL;
    const dim3 gQKV(24, M_TOTAL / 128);
    const dim3 gGemm(8, M_TOTAL / 128);
    const dim3 gAttn(SEQ / AQ, BATCH * NHEADS);
    const dim3 gWs(WN / 4 / 256, 6);

    wconv6_kernel<<<gWs, 256>>>(Wq, Wk, Wv, Wo, W1, W2, wh);
    ln_half_kernel<<<M_TOTAL, 256>>>(src, g1, be1, a);

    mm_gemm<<<gQKV, 256, MMG_SMEM>>>(a, wh, bq, bk, bv,
                                     nullptr, nullptr, q, k, v, 0);

    attn_mma<<<gAttn, 128, ATT_SMEM>>>(q, k, v, a);

    mm_gemm<<<gGemm, 256, MMG_SMEM>>>(a, wh + 3 * WN, bo, bo, bo,
                                      src, x1, nullptr, nullptr, nullptr, 0);

    ln_half_kernel<<<M_TOTAL, 256>>>(x1, g2, be2, a);
    mm_gemm<<<gGemm, 256, MMG_SMEM>>>(a, wh + 4 * WN, b1, b1, b1,
                                      nullptr, nullptr, h1, nullptr, nullptr, 1);

    mm_gemm<<<gGemm, 256, MMG_SMEM>>>(h1, wh + 5 * WN, b2, b2, b2,
                                      x1, out, nullptr, nullptr, nullptr, 0);
}

// round 16
// speedup vs baseline: 1.0273x; 1.0273x over previous
#include <cuda_runtime.h>
#include <cuda_fp16.h>
#include <math.h>
#include <stdint.h>

#define D_MODEL 1024
#define SEQ     2048
#define BATCH   4
#define NHEADS  16
#define HDIM    64
#define M_TOTAL (BATCH * SEQ)      // 8192
#define LN_EPS  1e-5f

// ---------------------------------------------------------------------------
// Scratch buffers (allocation-free rule: __device__ globals)
// ---------------------------------------------------------------------------
__device__ float  g_x1 [M_TOTAL * D_MODEL];
__device__ __half g_a  [M_TOTAL * D_MODEL];
__device__ __half g_q  [M_TOTAL * D_MODEL];
__device__ __half g_k  [M_TOTAL * D_MODEL];
__device__ __half g_v  [M_TOTAL * D_MODEL];
__device__ __half g_h1 [M_TOTAL * D_MODEL];
__device__ __half g_wh [6 * D_MODEL * D_MODEL];

// ---------------------------------------------------------------------------
// Helpers (sm_80+ ISA: mma.sync / ldmatrix / cp.async)
// ---------------------------------------------------------------------------
__device__ __forceinline__ uint32_t smem_u32(const void* p) {
    uint32_t a;
    asm("{ .reg .u64 t; cvta.to.shared.u64 t, %1; cvt.u32.u64 %0, t; }" : "=r"(a) : "l"(p));
    return a;
}
#define CP_ASYNC16(sa, g) \
    asm volatile("cp.async.cg.shared.global [%0], [%1], 16;" :: "r"(sa), "l"(g) : "memory")
#define CP_COMMIT() asm volatile("cp.async.commit_group;" ::: "memory")
#define CP_WAIT0()  asm volatile("cp.async.wait_group 0;" ::: "memory")
#define CP_WAIT1()  asm volatile("cp.async.wait_group 1;" ::: "memory")

__device__ __forceinline__ void ldsm4(uint32_t* r, uint32_t addr) {
    asm volatile("ldmatrix.sync.aligned.m8n8.x4.shared.b16 {%0,%1,%2,%3}, [%4];"
                 : "=r"(r[0]), "=r"(r[1]), "=r"(r[2]), "=r"(r[3]) : "r"(addr));
}
__device__ __forceinline__ void ldsm4t(uint32_t* r, uint32_t addr) {
    asm volatile("ldmatrix.sync.aligned.m8n8.x4.trans.shared.b16 {%0,%1,%2,%3}, [%4];"
                 : "=r"(r[0]), "=r"(r[1]), "=r"(r[2]), "=r"(r[3]) : "r"(addr));
}
// f32-accumulator HMMA
__device__ __forceinline__ void mma_f16(float* d, const uint32_t* a, const uint32_t* b) {
    asm volatile("mma.sync.aligned.m16n8k16.row.col.f32.f16.f16.f32 "
                 "{%0,%1,%2,%3}, {%4,%5,%6,%7}, {%8,%9}, {%0,%1,%2,%3};"
                 : "+f"(d[0]), "+f"(d[1]), "+f"(d[2]), "+f"(d[3])
                 : "r"(a[0]), "r"(a[1]), "r"(a[2]), "r"(a[3]), "r"(b[0]), "r"(b[1]));
}
// f16-accumulator HMMA (2x rate)
__device__ __forceinline__ void mma_f16h(uint32_t* d, const uint32_t* a, const uint32_t* b) {
    asm volatile("mma.sync.aligned.m16n8k16.row.col.f16.f16.f16.f16 "
                 "{%0,%1}, {%2,%3,%4,%5}, {%6,%7}, {%0,%1};"
                 : "+r"(d[0]), "+r"(d[1])
                 : "r"(a[0]), "r"(a[1]), "r"(a[2]), "r"(a[3]), "r"(b[0]), "r"(b[1]));
}
#define EX2(d, x) asm("ex2.approx.ftz.f32 %0, %1;" : "=f"(d) : "f"(x))

__device__ __forceinline__ uint32_t packh2(float v0, float v1) {
    __half2 t = __floats2half2_rn(v0, v1);
    return *(uint32_t*)&t;
}
__device__ __forceinline__ uint32_t maxh2(uint32_t a, uint32_t b) {
    uint32_t d;
    asm("max.f16x2 %0, %1, %2;" : "=r"(d) : "r"(a), "r"(b));
    return d;
}
__device__ __forceinline__ uint32_t hfma2r(uint32_t a, uint32_t b, uint32_t c) {
    uint32_t d;
    asm("fma.rn.f16x2 %0, %1, %2, %3;" : "=r"(d) : "r"(a), "r"(b), "r"(c));
    return d;
}
__device__ __forceinline__ uint32_t ex2h2(uint32_t a) {
    uint32_t d;
    asm("ex2.approx.f16x2 %0, %1;" : "=r"(d) : "r"(a));
    return d;
}

// ---------------------------------------------------------------------------
// All six weight conversions (fp32 -> fp16) in one launch
// ---------------------------------------------------------------------------
__global__ void __launch_bounds__(256) wconv6_kernel(
    const float* __restrict__ w0, const float* __restrict__ w1,
    const float* __restrict__ w2, const float* __restrict__ w3,
    const float* __restrict__ w4, const float* __restrict__ w5,
    __half* __restrict__ dst)
{
    const int ws = blockIdx.y;
    const float* src = (ws == 0) ? w0 : (ws == 1) ? w1 : (ws == 2) ? w2
                     : (ws == 3) ? w3 : (ws == 4) ? w4 : w5;
    const int i = blockIdx.x * 256 + threadIdx.x;
    const float4 v = ((const float4*)src)[i];
    const size_t base = (size_t)ws * (D_MODEL * D_MODEL / 2) + 2 * i;
    ((uint32_t*)dst)[base]     = packh2(v.x, v.y);
    ((uint32_t*)dst)[base + 1] = packh2(v.z, v.w);
}

// ---------------------------------------------------------------------------
// Fused LayerNorm -> single fp16
// ---------------------------------------------------------------------------
__global__ void __launch_bounds__(256) ln_half_kernel(
    const float* __restrict__ x, const float* __restrict__ g,
    const float* __restrict__ b, __half* __restrict__ y)
{
    __shared__ float red[16];
    const int row = blockIdx.x;
    const int tid = threadIdx.x;
    const float4 v = ((const float4*)(x + (size_t)row * D_MODEL))[tid];

    float s  = v.x + v.y + v.z + v.w;
    float ss = v.x * v.x + v.y * v.y + v.z * v.z + v.w * v.w;
    #pragma unroll
    for (int o = 16; o; o >>= 1) {
        s  += __shfl_xor_sync(0xffffffffu, s,  o);
        ss += __shfl_xor_sync(0xffffffffu, ss, o);
    }
    const int wid = tid >> 5;
    if ((tid & 31) == 0) { red[wid] = s; red[8 + wid] = ss; }
    __syncthreads();
    float S = 0.f, SS = 0.f;
    #pragma unroll
    for (int w = 0; w < 8; w++) { S += red[w]; SS += red[8 + w]; }
    const float mu   = S * (1.0f / D_MODEL);
    const float var  = SS * (1.0f / D_MODEL) - mu * mu;
    const float rstd = rsqrtf(var + LN_EPS);

    const float4 gv = ((const float4*)g)[tid];
    const float4 bv = ((const float4*)b)[tid];
    const float o0 = (v.x - mu) * rstd * gv.x + bv.x;
    const float o1 = (v.y - mu) * rstd * gv.y + bv.y;
    const float o2 = (v.z - mu) * rstd * gv.z + bv.z;
    const float o3 = (v.w - mu) * rstd * gv.w + bv.w;
    const size_t base = (size_t)row * (D_MODEL / 2) + tid * 2;
    ((uint32_t*)y)[base]     = packh2(o0, o1);
    ((uint32_t*)y)[base + 1] = packh2(o2, o3);
}

// ---------------------------------------------------------------------------
// fp16 GEMM (R10 shape) with hoisted epilogue bias loads
// ---------------------------------------------------------------------------
#define TILE_B   16384
#define STAGE_B  (2 * TILE_B)           // A, W = 32KB
#define MMG_SMEM (2 * STAGE_B)          // 65536

__device__ __forceinline__ uint32_t swadr(uint32_t tbase, int row, int chunk) {
    return tbase + row * 128 + (((chunk ^ row) & 7) << 4) + ((chunk & ~7) << 4);
}

__global__ void __launch_bounds__(256, 2)
mm_gemm(const __half* __restrict__ A, const __half* __restrict__ W,
        const float* __restrict__ bias0, const float* __restrict__ bias1,
        const float* __restrict__ bias2, const float* __restrict__ res,
        float* __restrict__ Cf, __half* __restrict__ C0,
        __half* __restrict__ C1, __half* __restrict__ C2, int doRelu)
{
    extern __shared__ char smem[];
    const uint32_t sb = smem_u32(smem);
    const int tid = threadIdx.x;
    const int wid = tid >> 5;
    const int lid = tid & 31;
    const int warpM = wid >> 2;
    const int warpN = wid & 3;
    const int grp = blockIdx.x >> 3;
    const int cn  = (blockIdx.x & 7) * 128;
    const int bm  = blockIdx.y * 128;

    const float* bias = (grp == 0) ? bias0 : (grp == 1) ? bias1 : bias2;
    __half* Ch = (grp == 0) ? C0 : (grp == 1) ? C1 : C2;

    const __half* baseA = A + (size_t)bm * 1024;
    const __half* baseW = W + (size_t)blockIdx.x * 128 * 1024;

    #define LOAD_CHUNK(stg, k0) do {                                              \
        const uint32_t _sbase = sb + (stg) * STAGE_B;                             \
        _Pragma("unroll")                                                         \
        for (int i = 0; i < 8; i++) {                                             \
            const int tile = i >> 2;                                              \
            const int idx  = (tid + i * 256) & 1023;                              \
            const int r    = idx >> 3;                                            \
            const int c8   = idx & 7;                                             \
            const __half* gp = (tile == 0 ? baseA : baseW)                        \
                + (size_t)r * 1024 + (k0) + c8 * 8;                               \
            const uint32_t sa = _sbase + tile * TILE_B +                          \
                (uint32_t)(r * 128 + (((c8 ^ r) & 7) << 4));                      \
            CP_ASYNC16(sa, gp);                                                   \
        }                                                                         \
        CP_COMMIT();                                                              \
    } while (0)

    float acc[4][4][4];
    #pragma unroll
    for (int a = 0; a < 4; a++)
        #pragma unroll
        for (int b = 0; b < 4; b++)
            #pragma unroll
            for (int c = 0; c < 4; c++) acc[a][b][c] = 0.f;

    const int aRow = warpM * 64 + (lid & 15);
    const int aChk = lid >> 4;
    const int bRow = warpN * 32 + ((lid >= 16) ? 8 : 0) + (lid & 7);
    const int bChk = (lid >> 3) & 1;

    LOAD_CHUNK(0, 0);

    #pragma unroll 1
    for (int c = 0; c < 16; c++) {
        const int s = c & 1;
        __syncthreads();
        if (c < 15) { LOAD_CHUNK(s ^ 1, (c + 1) * 64); CP_WAIT1(); }
        else        { CP_WAIT0(); }
        __syncthreads();

        const uint32_t sA = sb + s * STAGE_B;
        const uint32_t sW = sA + TILE_B;

        #pragma unroll
        for (int s16 = 0; s16 < 4; s16++) {
            const int kc = s16 * 2;
            uint32_t Bf[4][2];
            #pragma unroll
            for (int pair = 0; pair < 2; pair++)
                ldsm4(&Bf[pair * 2][0], swadr(sW, bRow + pair * 16, kc + bChk));
            #pragma unroll
            for (int mt = 0; mt < 4; mt++) {
                uint32_t Af[4];
                ldsm4(Af, swadr(sA, aRow + mt * 16, kc + aChk));
                #pragma unroll
                for (int nt = 0; nt < 4; nt++)
                    mma_f16(acc[mt][nt], Af, Bf[nt]);
            }
        }
    }

    const int rowoff = lid >> 2;
    const int coloff = (lid & 3) * 2;
    // hoisted bias loads: 8 values, reused across all mt / half iterations
    float bb[4][2];
    #pragma unroll
    for (int nt = 0; nt < 4; nt++) {
        const int gn = cn + warpN * 32 + nt * 8 + coloff;
        bb[nt][0] = __ldg(&bias[gn]);
        bb[nt][1] = __ldg(&bias[gn + 1]);
    }
    #pragma unroll
    for (int mt = 0; mt < 4; mt++) {
        #pragma unroll
        for (int nt = 0; nt < 4; nt++) {
            const int gn = cn + warpN * 32 + nt * 8 + coloff;
            #pragma unroll
            for (int half = 0; half < 2; half++) {
                const int gm = bm + warpM * 64 + mt * 16 + rowoff + half * 8;
                float v0 = acc[mt][nt][half * 2 + 0] + bb[nt][0];
                float v1 = acc[mt][nt][half * 2 + 1] + bb[nt][1];
                if (doRelu) { v0 = fmaxf(v0, 0.f); v1 = fmaxf(v1, 0.f); }
                const size_t off = (size_t)gm * 1024 + gn;
                if (res) {
                    const float2 rv = *(const float2*)&res[off];
                    v0 += rv.x; v1 += rv.y;
                }
                if (Cf) *(float2*)&Cf[off] = make_float2(v0, v1);
                else    *(uint32_t*)&Ch[off] = packh2(v0, v1);
            }
        }
    }
}

// ---------------------------------------------------------------------------
// Flash attention v4 (R14 validated best): fp16 softmax path, f32-accum PV,
// l via P @ ones MMA. 4 warps x 32 query rows, 64-key tiles, 3-stage.
// ---------------------------------------------------------------------------
#define AQ 128
#define AK 64
#define ATT_ST   16384
#define ATT_STB  16384
#define ATT_SMEM (ATT_ST + 3 * ATT_STB)   // 65536

__device__ __forceinline__ void softmax_h(
    uint32_t sch[8][2], float& m0, float& m1, float o[8][4], float lacc[4],
    float csf, uint32_t cs2)
{
    uint32_t t0 = sch[0][0], t1 = sch[0][1];
    #pragma unroll
    for (int j = 1; j < 8; j++) { t0 = maxh2(t0, sch[j][0]); t1 = maxh2(t1, sch[j][1]); }
    uint32_t pm = maxh2(__byte_perm(t0, t1, 0x5410), __byte_perm(t0, t1, 0x7632));
    #pragma unroll
    for (int d = 1; d < 4; d <<= 1)
        pm = maxh2(pm, __shfl_xor_sync(0xffffffffu, pm, d));
    const __half2 pmh = *(const __half2*)&pm;
    const float mx0 = __low2float(pmh)  * csf;
    const float mx1 = __high2float(pmh) * csf;
    const float m0n = fmaxf(m0, mx0);
    const float m1n = fmaxf(m1, mx1);
    float s0, s1;
    EX2(s0, m0 - m0n);
    EX2(s1, m1 - m1n);
    m0 = m0n; m1 = m1n;

    const uint32_t nm0 = packh2(-m0n, -m0n);
    const uint32_t nm1 = packh2(-m1n, -m1n);
    #pragma unroll
    for (int j = 0; j < 8; j++) {
        sch[j][0] = ex2h2(hfma2r(sch[j][0], cs2, nm0));
        sch[j][1] = ex2h2(hfma2r(sch[j][1], cs2, nm1));
    }
    #pragma unroll
    for (int j = 0; j < 8; j++) {
        o[j][0] *= s0; o[j][1] *= s0;
        o[j][2] *= s1; o[j][3] *= s1;
    }
    lacc[0] *= s0; lacc[1] *= s0;
    lacc[2] *= s1; lacc[3] *= s1;
}

__global__ void __launch_bounds__(128, 2) attn_mma(
    const __half* __restrict__ Q, const __half* __restrict__ K,
    const __half* __restrict__ V, __half* __restrict__ O)
{
    extern __shared__ char smem[];
    const uint32_t sb = smem_u32(smem);
    const int tid = threadIdx.x;
    const int wid = tid >> 5;
    const int lid = tid & 31;
    const int bh  = blockIdx.y;
    const int b   = bh >> 4;
    const int h   = bh & 15;
    const int q0  = blockIdx.x * AQ;
    const size_t rowBase = (size_t)b * SEQ;
    const int hcol = h * HDIM;

    {
        #pragma unroll
        for (int i = 0; i < 8; i++) {
            const int idx = tid + i * 128;
            const int r   = idx >> 3;
            const int c8  = idx & 7;
            const __half* gp = Q + (rowBase + q0 + r) * 1024 + hcol + c8 * 8;
            const uint32_t sa = sb + (uint32_t)(r * 128 + (((c8 ^ r) & 7) << 4));
            CP_ASYNC16(sa, gp);
        }
        CP_COMMIT();
    }

    #define LOAD_KV(stg, kt) do {                                               \
        const uint32_t _sbase = sb + ATT_ST + (stg) * ATT_STB;                  \
        _Pragma("unroll")                                                       \
        for (int i = 0; i < 8; i++) {                                           \
            const int tile = i >> 2;                                            \
            const int idx  = (tid + (i & 3) * 128) & 511;                       \
            const int r    = idx >> 3;                                          \
            const int c8   = idx & 7;                                           \
            const __half* gp = (tile ? V : K)                                   \
                + (rowBase + (kt) * AK + r) * 1024 + hcol + c8 * 8;             \
            const uint32_t sa = _sbase + tile * 8192 +                          \
                (uint32_t)(r * 128 + (((c8 ^ r) & 7) << 4));                    \
            CP_ASYNC16(sa, gp);                                                 \
        }                                                                       \
        CP_COMMIT();                                                            \
    } while (0)

    LOAD_KV(0, 0);
    LOAD_KV(1, 1);
    CP_WAIT1();
    __syncthreads();

    uint32_t Qf0[4][4], Qf1[4][4];
    {
        const int r0 = wid * 32 + (lid & 15);
        const int ck = lid >> 4;
        #pragma unroll
        for (int t = 0; t < 4; t++) {
            ldsm4(Qf0[t], swadr(sb, r0,      2 * t + ck));
            ldsm4(Qf1[t], swadr(sb, r0 + 16, 2 * t + ck));
        }
    }

    float o0[8][4], o1[8][4], lacc0[4], lacc1[4];
    #pragma unroll
    for (int j = 0; j < 8; j++)
        #pragma unroll
        for (int e = 0; e < 4; e++) { o0[j][e] = 0.f; o1[j][e] = 0.f; }
    #pragma unroll
    for (int e = 0; e < 4; e++) { lacc0[e] = 0.f; lacc1[e] = 0.f; }
    float m00 = -INFINITY, m01 = -INFINITY, m10 = -INFINITY, m11 = -INFINITY;

    const float csf = __half2float(__float2half_rn(0.125f * 1.4426950408889634f));
    const uint32_t cs2 = packh2(csf, csf);
    const uint32_t onesb[2] = { 0x3C003C00u, 0x3C003C00u };   // packed 1.0h

    const int kRowL = ((lid >= 16) ? 8 : 0) + (lid & 7);
    const int kChkL = (lid >> 3) & 1;
    const int vT    = lid >> 3;
    const int vKeyL = ((vT & 1) << 3) + (lid & 7);
    const int vChkL = vT >> 1;

    #pragma unroll 1
    for (int kt = 0; kt < SEQ / AK; kt++) {
        if (kt > 0) {
            if (kt == SEQ / AK - 1) CP_WAIT0(); else CP_WAIT1();
            __syncthreads();
        }
        if (kt + 2 < SEQ / AK) LOAD_KV((kt + 2) % 3, kt + 2);

        const uint32_t sK = sb + ATT_ST + (kt % 3) * ATT_STB;
        const uint32_t sV = sK + 8192;

        // ---- S = Q K^T, f16 accumulators ----
        uint32_t sch0[8][2], sch1[8][2];
        #pragma unroll
        for (int j = 0; j < 8; j++) {
            sch0[j][0] = 0u; sch0[j][1] = 0u;
            sch1[j][0] = 0u; sch1[j][1] = 0u;
        }

        #pragma unroll
        for (int t = 0; t < 4; t++) {
            #pragma unroll
            for (int kp = 0; kp < 4; kp++) {
                uint32_t kf[4];
                ldsm4(kf, swadr(sK, kp * 16 + kRowL, 2 * t + kChkL));
                mma_f16h(sch0[2 * kp],     Qf0[t], kf);
                mma_f16h(sch0[2 * kp + 1], Qf0[t], kf + 2);
                mma_f16h(sch1[2 * kp],     Qf1[t], kf);
                mma_f16h(sch1[2 * kp + 1], Qf1[t], kf + 2);
            }
        }

        // ---- packed softmax (in-place: sch -> probs) ----
        softmax_h(sch0, m00, m01, o0, lacc0, csf, cs2);
        softmax_h(sch1, m10, m11, o1, lacc1, csf, cs2);

        // ---- O += P V ; l += P @ ones ----
        #pragma unroll
        for (int kb = 0; kb < 4; kb++) {
            const uint32_t pa0[4] = { sch0[2 * kb][0], sch0[2 * kb][1],
                                      sch0[2 * kb + 1][0], sch0[2 * kb + 1][1] };
            const uint32_t pa1[4] = { sch1[2 * kb][0], sch1[2 * kb][1],
                                      sch1[2 * kb + 1][0], sch1[2 * kb + 1][1] };
            mma_f16(lacc0, pa0, onesb);
            mma_f16(lacc1, pa1, onesb);
            #pragma unroll
            for (int np = 0; np < 4; np++) {
                uint32_t vf[4];
                ldsm4t(vf, swadr(sV, kb * 16 + vKeyL, np * 2 + vChkL));
                mma_f16(o0[2 * np],     pa0, vf);
                mma_f16(o0[2 * np + 1], pa0, vf + 2);
                mma_f16(o1[2 * np],     pa1, vf);
                mma_f16(o1[2 * np + 1], pa1, vf + 2);
            }
        }
    }

    // ---- epilogue: l comes straight from the ones-MMA (no shuffles) ----
    const int cb = hcol + (lid & 3) * 2;
    {
        const float il0 = 1.0f / lacc0[0];
        const float il1 = 1.0f / lacc0[2];
        const size_t row0 = rowBase + q0 + wid * 32 + (lid >> 2);
        const size_t row1 = row0 + 8;
        #pragma unroll
        for (int j = 0; j < 8; j++) {
            const int col = cb + j * 8;
            *(uint32_t*)&O[row0 * 1024 + col] = packh2(o0[j][0] * il0, o0[j][1] * il0);
            *(uint32_t*)&O[row1 * 1024 + col] = packh2(o0[j][2] * il1, o0[j][3] * il1);
        }
    }
    {
        const float il0 = 1.0f / lacc1[0];
        const float il1 = 1.0f / lacc1[2];
        const size_t row0 = rowBase + q0 + wid * 32 + 16 + (lid >> 2);
        const size_t row1 = row0 + 8;
        #pragma unroll
        for (int j = 0; j < 8; j++) {
            const int col = cb + j * 8;
            *(uint32_t*)&O[row0 * 1024 + col] = packh2(o1[j][0] * il0, o1[j][1] * il0);
            *(uint32_t*)&O[row1 * 1024 + col] = packh2(o1[j][2] * il1, o1[j][3] * il1);
        }
    }
}

// ---------------------------------------------------------------------------
// Launch
// ---------------------------------------------------------------------------
extern "C" void kernel_launch(void* const* d_in, const int* in_sizes, int n_in,
                              void* d_out, int out_size)
{
    const float* src = (const float*)d_in[0];
    const float* Wq  = (const float*)d_in[1];  const float* bq = (const float*)d_in[2];
    const float* Wk  = (const float*)d_in[3];  const float* bk = (const float*)d_in[4];
    const float* Wv  = (const float*)d_in[5];  const float* bv = (const float*)d_in[6];
    const float* Wo  = (const float*)d_in[7];  const float* bo = (const float*)d_in[8];
    const float* W1  = (const float*)d_in[9];  const float* b1 = (const float*)d_in[10];
    const float* W2  = (const float*)d_in[11]; const float* b2 = (const float*)d_in[12];
    const float* g1  = (const float*)d_in[13]; const float* be1 = (const float*)d_in[14];
    const float* g2  = (const float*)d_in[15]; const float* be2 = (const float*)d_in[16];
    float* out = (float*)d_out;

    float* x1;
    __half *a, *q, *k, *v, *h1, *wh;
    cudaGetSymbolAddress((void**)&x1, g_x1);
    cudaGetSymbolAddress((void**)&a,  g_a);
    cudaGetSymbolAddress((void**)&q,  g_q);
    cudaGetSymbolAddress((void**)&k,  g_k);
    cudaGetSymbolAddress((void**)&v,  g_v);
    cudaGetSymbolAddress((void**)&h1, g_h1);
    cudaGetSymbolAddress((void**)&wh, g_wh);

    cudaFuncSetAttribute(mm_gemm,  cudaFuncAttributeMaxDynamicSharedMemorySize, MMG_SMEM);
    cudaFuncSetAttribute(attn_mma, cudaFuncAttributeMaxDynamicSharedMemorySize, ATT_SMEM);

    const int WN = D_MODEL * D_MODEL;
    const dim3 gQKV(24, M_TOTAL / 128);
    const dim3 gGemm(8, M_TOTAL / 128);
    const dim3 gAttn(SEQ / AQ, BATCH * NHEADS);
    const dim3 gWs(WN / 4 / 256, 6);

    wconv6_kernel<<<gWs, 256>>>(Wq, Wk, Wv, Wo, W1, W2, wh);
    ln_half_kernel<<<M_TOTAL, 256>>>(src, g1, be1, a);

    mm_gemm<<<gQKV, 256, MMG_SMEM>>>(a, wh, bq, bk, bv,
                                     nullptr, nullptr, q, k, v, 0);

    attn_mma<<<gAttn, 128, ATT_SMEM>>>(q, k, v, a);

    mm_gemm<<<gGemm, 256, MMG_SMEM>>>(a, wh + 3 * WN, bo, bo, bo,
                                      src, x1, nullptr, nullptr, nullptr, 0);

    ln_half_kernel<<<M_TOTAL, 256>>>(x1, g2, be2, a);
    mm_gemm<<<gGemm, 256, MMG_SMEM>>>(a, wh + 4 * WN, b1, b1, b1,
                                      nullptr, nullptr, h1, nullptr, nullptr, 1);

    mm_gemm<<<gGemm, 256, MMG_SMEM>>>(h1, wh + 5 * WN, b2, b2, b2,
                                      x1, out, nullptr, nullptr, nullptr, 0);
}

// round 17
// speedup vs baseline: 1.0328x; 1.0053x over previous
#include <cuda_runtime.h>
#include <cuda_fp16.h>
#include <math.h>
#include <stdint.h>

#define D_MODEL 1024
#define SEQ     2048
#define BATCH   4
#define NHEADS  16
#define HDIM    64
#define M_TOTAL (BATCH * SEQ)      // 8192
#define LN_EPS  1e-5f

// ---------------------------------------------------------------------------
// Scratch buffers (allocation-free rule: __device__ globals)
// ---------------------------------------------------------------------------
__device__ float  g_x1 [M_TOTAL * D_MODEL];
__device__ __half g_a  [M_TOTAL * D_MODEL];
__device__ __half g_q  [M_TOTAL * D_MODEL];
__device__ __half g_k  [M_TOTAL * D_MODEL];
__device__ __half g_v  [M_TOTAL * D_MODEL];
__device__ __half g_h1 [M_TOTAL * D_MODEL];
__device__ __half g_wh [6 * D_MODEL * D_MODEL];

// ---------------------------------------------------------------------------
// Helpers (sm_80+ ISA: mma.sync / ldmatrix / cp.async)
// ---------------------------------------------------------------------------
__device__ __forceinline__ uint32_t smem_u32(const void* p) {
    uint32_t a;
    asm("{ .reg .u64 t; cvta.to.shared.u64 t, %1; cvt.u32.u64 %0, t; }" : "=r"(a) : "l"(p));
    return a;
}
#define CP_ASYNC16(sa, g) \
    asm volatile("cp.async.cg.shared.global [%0], [%1], 16;" :: "r"(sa), "l"(g) : "memory")
#define CP_COMMIT() asm volatile("cp.async.commit_group;" ::: "memory")
#define CP_WAIT0()  asm volatile("cp.async.wait_group 0;" ::: "memory")
#define CP_WAIT1()  asm volatile("cp.async.wait_group 1;" ::: "memory")
#define CP_WAIT2()  asm volatile("cp.async.wait_group 2;" ::: "memory")

__device__ __forceinline__ void ldsm4(uint32_t* r, uint32_t addr) {
    asm volatile("ldmatrix.sync.aligned.m8n8.x4.shared.b16 {%0,%1,%2,%3}, [%4];"
                 : "=r"(r[0]), "=r"(r[1]), "=r"(r[2]), "=r"(r[3]) : "r"(addr));
}
__device__ __forceinline__ void ldsm4t(uint32_t* r, uint32_t addr) {
    asm volatile("ldmatrix.sync.aligned.m8n8.x4.trans.shared.b16 {%0,%1,%2,%3}, [%4];"
                 : "=r"(r[0]), "=r"(r[1]), "=r"(r[2]), "=r"(r[3]) : "r"(addr));
}
// f32-accumulator HMMA
__device__ __forceinline__ void mma_f16(float* d, const uint32_t* a, const uint32_t* b) {
    asm volatile("mma.sync.aligned.m16n8k16.row.col.f32.f16.f16.f32 "
                 "{%0,%1,%2,%3}, {%4,%5,%6,%7}, {%8,%9}, {%0,%1,%2,%3};"
                 : "+f"(d[0]), "+f"(d[1]), "+f"(d[2]), "+f"(d[3])
                 : "r"(a[0]), "r"(a[1]), "r"(a[2]), "r"(a[3]), "r"(b[0]), "r"(b[1]));
}
// f16-accumulator HMMA (2x rate)
__device__ __forceinline__ void mma_f16h(uint32_t* d, const uint32_t* a, const uint32_t* b) {
    asm volatile("mma.sync.aligned.m16n8k16.row.col.f16.f16.f16.f16 "
                 "{%0,%1}, {%2,%3,%4,%5}, {%6,%7}, {%0,%1};"
                 : "+r"(d[0]), "+r"(d[1])
                 : "r"(a[0]), "r"(a[1]), "r"(a[2]), "r"(a[3]), "r"(b[0]), "r"(b[1]));
}
#define EX2(d, x) asm("ex2.approx.ftz.f32 %0, %1;" : "=f"(d) : "f"(x))

__device__ __forceinline__ uint32_t packh2(float v0, float v1) {
    __half2 t = __floats2half2_rn(v0, v1);
    return *(uint32_t*)&t;
}
__device__ __forceinline__ uint32_t maxh2(uint32_t a, uint32_t b) {
    uint32_t d;
    asm("max.f16x2 %0, %1, %2;" : "=r"(d) : "r"(a), "r"(b));
    return d;
}
__device__ __forceinline__ uint32_t hfma2r(uint32_t a, uint32_t b, uint32_t c) {
    uint32_t d;
    asm("fma.rn.f16x2 %0, %1, %2, %3;" : "=r"(d) : "r"(a), "r"(b), "r"(c));
    return d;
}
__device__ __forceinline__ uint32_t ex2h2(uint32_t a) {
    uint32_t d;
    asm("ex2.approx.f16x2 %0, %1;" : "=r"(d) : "r"(a));
    return d;
}

// ---------------------------------------------------------------------------
// All six weight conversions (fp32 -> fp16) in one launch
// ---------------------------------------------------------------------------
__global__ void __launch_bounds__(256) wconv6_kernel(
    const float* __restrict__ w0, const float* __restrict__ w1,
    const float* __restrict__ w2, const float* __restrict__ w3,
    const float* __restrict__ w4, const float* __restrict__ w5,
    __half* __restrict__ dst)
{
    const int ws = blockIdx.y;
    const float* src = (ws == 0) ? w0 : (ws == 1) ? w1 : (ws == 2) ? w2
                     : (ws == 3) ? w3 : (ws == 4) ? w4 : w5;
    const int i = blockIdx.x * 256 + threadIdx.x;
    const float4 v = ((const float4*)src)[i];
    const size_t base = (size_t)ws * (D_MODEL * D_MODEL / 2) + 2 * i;
    ((uint32_t*)dst)[base]     = packh2(v.x, v.y);
    ((uint32_t*)dst)[base + 1] = packh2(v.z, v.w);
}

// ---------------------------------------------------------------------------
// Fused LayerNorm -> single fp16
// ---------------------------------------------------------------------------
__global__ void __launch_bounds__(256) ln_half_kernel(
    const float* __restrict__ x, const float* __restrict__ g,
    const float* __restrict__ b, __half* __restrict__ y)
{
    __shared__ float red[16];
    const int row = blockIdx.x;
    const int tid = threadIdx.x;
    const float4 v = ((const float4*)(x + (size_t)row * D_MODEL))[tid];

    float s  = v.x + v.y + v.z + v.w;
    float ss = v.x * v.x + v.y * v.y + v.z * v.z + v.w * v.w;
    #pragma unroll
    for (int o = 16; o; o >>= 1) {
        s  += __shfl_xor_sync(0xffffffffu, s,  o);
        ss += __shfl_xor_sync(0xffffffffu, ss, o);
    }
    const int wid = tid >> 5;
    if ((tid & 31) == 0) { red[wid] = s; red[8 + wid] = ss; }
    __syncthreads();
    float S = 0.f, SS = 0.f;
    #pragma unroll
    for (int w = 0; w < 8; w++) { S += red[w]; SS += red[8 + w]; }
    const float mu   = S * (1.0f / D_MODEL);
    const float var  = SS * (1.0f / D_MODEL) - mu * mu;
    const float rstd = rsqrtf(var + LN_EPS);

    const float4 gv = ((const float4*)g)[tid];
    const float4 bv = ((const float4*)b)[tid];
    const float o0 = (v.x - mu) * rstd * gv.x + bv.x;
    const float o1 = (v.y - mu) * rstd * gv.y + bv.y;
    const float o2 = (v.z - mu) * rstd * gv.z + bv.z;
    const float o3 = (v.w - mu) * rstd * gv.w + bv.w;
    const size_t base = (size_t)row * (D_MODEL / 2) + tid * 2;
    ((uint32_t*)y)[base]     = packh2(o0, o1);
    ((uint32_t*)y)[base + 1] = packh2(o2, o3);
}

// ---------------------------------------------------------------------------
// fp16 GEMM (R16: 8 warps, 64x32 warp tiles, 2-stage, hoisted bias) — pinned
// ---------------------------------------------------------------------------
#define TILE_B   16384
#define STAGE_B  (2 * TILE_B)           // A, W = 32KB
#define MMG_SMEM (2 * STAGE_B)          // 65536

__device__ __forceinline__ uint32_t swadr(uint32_t tbase, int row, int chunk) {
    return tbase + row * 128 + (((chunk ^ row) & 7) << 4) + ((chunk & ~7) << 4);
}

__global__ void __launch_bounds__(256, 2)
mm_gemm(const __half* __restrict__ A, const __half* __restrict__ W,
        const float* __restrict__ bias0, const float* __restrict__ bias1,
        const float* __restrict__ bias2, const float* __restrict__ res,
        float* __restrict__ Cf, __half* __restrict__ C0,
        __half* __restrict__ C1, __half* __restrict__ C2, int doRelu)
{
    extern __shared__ char smem[];
    const uint32_t sb = smem_u32(smem);
    const int tid = threadIdx.x;
    const int wid = tid >> 5;
    const int lid = tid & 31;
    const int warpM = wid >> 2;
    const int warpN = wid & 3;
    const int grp = blockIdx.x >> 3;
    const int cn  = (blockIdx.x & 7) * 128;
    const int bm  = blockIdx.y * 128;

    const float* bias = (grp == 0) ? bias0 : (grp == 1) ? bias1 : bias2;
    __half* Ch = (grp == 0) ? C0 : (grp == 1) ? C1 : C2;

    const __half* baseA = A + (size_t)bm * 1024;
    const __half* baseW = W + (size_t)blockIdx.x * 128 * 1024;

    #define LOAD_CHUNK(stg, k0) do {                                              \
        const uint32_t _sbase = sb + (stg) * STAGE_B;                             \
        _Pragma("unroll")                                                         \
        for (int i = 0; i < 8; i++) {                                             \
            const int tile = i >> 2;                                              \
            const int idx  = (tid + i * 256) & 1023;                              \
            const int r    = idx >> 3;                                            \
            const int c8   = idx & 7;                                             \
            const __half* gp = (tile == 0 ? baseA : baseW)                        \
                + (size_t)r * 1024 + (k0) + c8 * 8;                               \
            const uint32_t sa = _sbase + tile * TILE_B +                          \
                (uint32_t)(r * 128 + (((c8 ^ r) & 7) << 4));                      \
            CP_ASYNC16(sa, gp);                                                   \
        }                                                                         \
        CP_COMMIT();                                                              \
    } while (0)

    float acc[4][4][4];
    #pragma unroll
    for (int a = 0; a < 4; a++)
        #pragma unroll
        for (int b = 0; b < 4; b++)
            #pragma unroll
            for (int c = 0; c < 4; c++) acc[a][b][c] = 0.f;

    const int aRow = warpM * 64 + (lid & 15);
    const int aChk = lid >> 4;
    const int bRow = warpN * 32 + ((lid >= 16) ? 8 : 0) + (lid & 7);
    const int bChk = (lid >> 3) & 1;

    LOAD_CHUNK(0, 0);

    #pragma unroll 1
    for (int c = 0; c < 16; c++) {
        const int s = c & 1;
        __syncthreads();
        if (c < 15) { LOAD_CHUNK(s ^ 1, (c + 1) * 64); CP_WAIT1(); }
        else        { CP_WAIT0(); }
        __syncthreads();

        const uint32_t sA = sb + s * STAGE_B;
        const uint32_t sW = sA + TILE_B;

        #pragma unroll
        for (int s16 = 0; s16 < 4; s16++) {
            const int kc = s16 * 2;
            uint32_t Bf[4][2];
            #pragma unroll
            for (int pair = 0; pair < 2; pair++)
                ldsm4(&Bf[pair * 2][0], swadr(sW, bRow + pair * 16, kc + bChk));
            #pragma unroll
            for (int mt = 0; mt < 4; mt++) {
                uint32_t Af[4];
                ldsm4(Af, swadr(sA, aRow + mt * 16, kc + aChk));
                #pragma unroll
                for (int nt = 0; nt < 4; nt++)
                    mma_f16(acc[mt][nt], Af, Bf[nt]);
            }
        }
    }

    const int rowoff = lid >> 2;
    const int coloff = (lid & 3) * 2;
    float bb[4][2];
    #pragma unroll
    for (int nt = 0; nt < 4; nt++) {
        const int gn = cn + warpN * 32 + nt * 8 + coloff;
        bb[nt][0] = __ldg(&bias[gn]);
        bb[nt][1] = __ldg(&bias[gn + 1]);
    }
    #pragma unroll
    for (int mt = 0; mt < 4; mt++) {
        #pragma unroll
        for (int nt = 0; nt < 4; nt++) {
            const int gn = cn + warpN * 32 + nt * 8 + coloff;
            #pragma unroll
            for (int half = 0; half < 2; half++) {
                const int gm = bm + warpM * 64 + mt * 16 + rowoff + half * 8;
                float v0 = acc[mt][nt][half * 2 + 0] + bb[nt][0];
                float v1 = acc[mt][nt][half * 2 + 1] + bb[nt][1];
                if (doRelu) { v0 = fmaxf(v0, 0.f); v1 = fmaxf(v1, 0.f); }
                const size_t off = (size_t)gm * 1024 + gn;
                if (res) {
                    const float2 rv = *(const float2*)&res[off];
                    v0 += rv.x; v1 += rv.y;
                }
                if (Cf) *(float2*)&Cf[off] = make_float2(v0, v1);
                else    *(uint32_t*)&Ch[off] = packh2(v0, v1);
            }
        }
    }
}

// ---------------------------------------------------------------------------
// Flash attention (R14/R16 math, byte-identical loop body) with a 4-stage
// KV ring: two tiles in flight (wait_group 2) for deeper latency cover.
// smem: Q 16KB | 4 stages x (K 8KB + V 8KB) = 80KB; 2 CTAs/SM (160KB).
// ---------------------------------------------------------------------------
#define AQ 128
#define AK 64
#define ATT_ST   16384
#define ATT_STB  16384
#define ATT_NST  4
#define ATT_SMEM (ATT_ST + ATT_NST * ATT_STB)   // 81920

__device__ __forceinline__ void softmax_h(
    uint32_t sch[8][2], float& m0, float& m1, float o[8][4], float lacc[4],
    float csf, uint32_t cs2)
{
    uint32_t t0 = sch[0][0], t1 = sch[0][1];
    #pragma unroll
    for (int j = 1; j < 8; j++) { t0 = maxh2(t0, sch[j][0]); t1 = maxh2(t1, sch[j][1]); }
    uint32_t pm = maxh2(__byte_perm(t0, t1, 0x5410), __byte_perm(t0, t1, 0x7632));
    #pragma unroll
    for (int d = 1; d < 4; d <<= 1)
        pm = maxh2(pm, __shfl_xor_sync(0xffffffffu, pm, d));
    const __half2 pmh = *(const __half2*)&pm;
    const float mx0 = __low2float(pmh)  * csf;
    const float mx1 = __high2float(pmh) * csf;
    const float m0n = fmaxf(m0, mx0);
    const float m1n = fmaxf(m1, mx1);
    float s0, s1;
    EX2(s0, m0 - m0n);
    EX2(s1, m1 - m1n);
    m0 = m0n; m1 = m1n;

    const uint32_t nm0 = packh2(-m0n, -m0n);
    const uint32_t nm1 = packh2(-m1n, -m1n);
    #pragma unroll
    for (int j = 0; j < 8; j++) {
        sch[j][0] = ex2h2(hfma2r(sch[j][0], cs2, nm0));
        sch[j][1] = ex2h2(hfma2r(sch[j][1], cs2, nm1));
    }
    #pragma unroll
    for (int j = 0; j < 8; j++) {
        o[j][0] *= s0; o[j][1] *= s0;
        o[j][2] *= s1; o[j][3] *= s1;
    }
    lacc[0] *= s0; lacc[1] *= s0;
    lacc[2] *= s1; lacc[3] *= s1;
}

__global__ void __launch_bounds__(128, 2) attn_mma(
    const __half* __restrict__ Q, const __half* __restrict__ K,
    const __half* __restrict__ V, __half* __restrict__ O)
{
    extern __shared__ char smem[];
    const uint32_t sb = smem_u32(smem);
    const int tid = threadIdx.x;
    const int wid = tid >> 5;
    const int lid = tid & 31;
    const int bh  = blockIdx.y;
    const int b   = bh >> 4;
    const int h   = bh & 15;
    const int q0  = blockIdx.x * AQ;
    const size_t rowBase = (size_t)b * SEQ;
    const int hcol = h * HDIM;

    {
        #pragma unroll
        for (int i = 0; i < 8; i++) {
            const int idx = tid + i * 128;
            const int r   = idx >> 3;
            const int c8  = idx & 7;
            const __half* gp = Q + (rowBase + q0 + r) * 1024 + hcol + c8 * 8;
            const uint32_t sa = sb + (uint32_t)(r * 128 + (((c8 ^ r) & 7) << 4));
            CP_ASYNC16(sa, gp);
        }
        CP_COMMIT();
    }

    #define LOAD_KV(stg, kt) do {                                               \
        const uint32_t _sbase = sb + ATT_ST + (stg) * ATT_STB;                  \
        _Pragma("unroll")                                                       \
        for (int i = 0; i < 8; i++) {                                           \
            const int tile = i >> 2;                                            \
            const int idx  = (tid + (i & 3) * 128) & 511;                       \
            const int r    = idx >> 3;                                          \
            const int c8   = idx & 7;                                           \
            const __half* gp = (tile ? V : K)                                   \
                + (rowBase + (kt) * AK + r) * 1024 + hcol + c8 * 8;             \
            const uint32_t sa = _sbase + tile * 8192 +                          \
                (uint32_t)(r * 128 + (((c8 ^ r) & 7) << 4));                    \
            CP_ASYNC16(sa, gp);                                                 \
        }                                                                       \
        CP_COMMIT();                                                            \
    } while (0)

    LOAD_KV(0, 0);
    LOAD_KV(1, 1);
    LOAD_KV(2, 2);
    CP_WAIT2();                 // Q + KV0 complete; KV1/KV2 may be in flight
    __syncthreads();

    uint32_t Qf0[4][4], Qf1[4][4];
    {
        const int r0 = wid * 32 + (lid & 15);
        const int ck = lid >> 4;
        #pragma unroll
        for (int t = 0; t < 4; t++) {
            ldsm4(Qf0[t], swadr(sb, r0,      2 * t + ck));
            ldsm4(Qf1[t], swadr(sb, r0 + 16, 2 * t + ck));
        }
    }

    float o0[8][4], o1[8][4], lacc0[4], lacc1[4];
    #pragma unroll
    for (int j = 0; j < 8; j++)
        #pragma unroll
        for (int e = 0; e < 4; e++) { o0[j][e] = 0.f; o1[j][e] = 0.f; }
    #pragma unroll
    for (int e = 0; e < 4; e++) { lacc0[e] = 0.f; lacc1[e] = 0.f; }
    float m00 = -INFINITY, m01 = -INFINITY, m10 = -INFINITY, m11 = -INFINITY;

    const float csf = __half2float(__float2half_rn(0.125f * 1.4426950408889634f));
    const uint32_t cs2 = packh2(csf, csf);
    const uint32_t onesb[2] = { 0x3C003C00u, 0x3C003C00u };   // packed 1.0h

    const int kRowL = ((lid >= 16) ? 8 : 0) + (lid & 7);
    const int kChkL = (lid >> 3) & 1;
    const int vT    = lid >> 3;
    const int vKeyL = ((vT & 1) << 3) + (lid & 7);
    const int vChkL = vT >> 1;

    #pragma unroll 1
    for (int kt = 0; kt < SEQ / AK; kt++) {
        if (kt > 0) {
            // pending groups after this wait: KV_{kt+1}, KV_{kt+2} (if issued)
            if (kt + 2 < SEQ / AK)      CP_WAIT2();
            else if (kt + 1 < SEQ / AK) CP_WAIT1();
            else                        CP_WAIT0();
            __syncthreads();
        }
        if (kt + 3 < SEQ / AK) LOAD_KV((kt + 3) & 3, kt + 3);

        const uint32_t sK = sb + ATT_ST + (kt & 3) * ATT_STB;
        const uint32_t sV = sK + 8192;

        // ---- S = Q K^T, f16 accumulators ----
        uint32_t sch0[8][2], sch1[8][2];
        #pragma unroll
        for (int j = 0; j < 8; j++) {
            sch0[j][0] = 0u; sch0[j][1] = 0u;
            sch1[j][0] = 0u; sch1[j][1] = 0u;
        }

        #pragma unroll
        for (int t = 0; t < 4; t++) {
            #pragma unroll
            for (int kp = 0; kp < 4; kp++) {
                uint32_t kf[4];
                ldsm4(kf, swadr(sK, kp * 16 + kRowL, 2 * t + kChkL));
                mma_f16h(sch0[2 * kp],     Qf0[t], kf);
                mma_f16h(sch0[2 * kp + 1], Qf0[t], kf + 2);
                mma_f16h(sch1[2 * kp],     Qf1[t], kf);
                mma_f16h(sch1[2 * kp + 1], Qf1[t], kf + 2);
            }
        }

        // ---- packed softmax (in-place: sch -> probs) ----
        softmax_h(sch0, m00, m01, o0, lacc0, csf, cs2);
        softmax_h(sch1, m10, m11, o1, lacc1, csf, cs2);

        // ---- O += P V ; l += P @ ones ----
        #pragma unroll
        for (int kb = 0; kb < 4; kb++) {
            const uint32_t pa0[4] = { sch0[2 * kb][0], sch0[2 * kb][1],
                                      sch0[2 * kb + 1][0], sch0[2 * kb + 1][1] };
            const uint32_t pa1[4] = { sch1[2 * kb][0], sch1[2 * kb][1],
                                      sch1[2 * kb + 1][0], sch1[2 * kb + 1][1] };
            mma_f16(lacc0, pa0, onesb);
            mma_f16(lacc1, pa1, onesb);
            #pragma unroll
            for (int np = 0; np < 4; np++) {
                uint32_t vf[4];
                ldsm4t(vf, swadr(sV, kb * 16 + vKeyL, np * 2 + vChkL));
                mma_f16(o0[2 * np],     pa0, vf);
                mma_f16(o0[2 * np + 1], pa0, vf + 2);
                mma_f16(o1[2 * np],     pa1, vf);
                mma_f16(o1[2 * np + 1], pa1, vf + 2);
            }
        }
    }

    // ---- epilogue: l comes straight from the ones-MMA (no shuffles) ----
    const int cb = hcol + (lid & 3) * 2;
    {
        const float il0 = 1.0f / lacc0[0];
        const float il1 = 1.0f / lacc0[2];
        const size_t row0 = rowBase + q0 + wid * 32 + (lid >> 2);
        const size_t row1 = row0 + 8;
        #pragma unroll
        for (int j = 0; j < 8; j++) {
            const int col = cb + j * 8;
            *(uint32_t*)&O[row0 * 1024 + col] = packh2(o0[j][0] * il0, o0[j][1] * il0);
            *(uint32_t*)&O[row1 * 1024 + col] = packh2(o0[j][2] * il1, o0[j][3] * il1);
        }
    }
    {
        const float il0 = 1.0f / lacc1[0];
        const float il1 = 1.0f / lacc1[2];
        const size_t row0 = rowBase + q0 + wid * 32 + 16 + (lid >> 2);
        const size_t row1 = row0 + 8;
        #pragma unroll
        for (int j = 0; j < 8; j++) {
            const int col = cb + j * 8;
            *(uint32_t*)&O[row0 * 1024 + col] = packh2(o1[j][0] * il0, o1[j][1] * il0);
            *(uint32_t*)&O[row1 * 1024 + col] = packh2(o1[j][2] * il1, o1[j][3] * il1);
        }
    }
}

// ---------------------------------------------------------------------------
// Launch
// ---------------------------------------------------------------------------
extern "C" void kernel_launch(void* const* d_in, const int* in_sizes, int n_in,
                              void* d_out, int out_size)
{
    const float* src = (const float*)d_in[0];
    const float* Wq  = (const float*)d_in[1];  const float* bq = (const float*)d_in[2];
    const float* Wk  = (const float*)d_in[3];  const float* bk = (const float*)d_in[4];
    const float* Wv  = (const float*)d_in[5];  const float* bv = (const float*)d_in[6];
    const float* Wo  = (const float*)d_in[7];  const float* bo = (const float*)d_in[8];
    const float* W1  = (const float*)d_in[9];  const float* b1 = (const float*)d_in[10];
    const float* W2  = (const float*)d_in[11]; const float* b2 = (const float*)d_in[12];
    const float* g1  = (const float*)d_in[13]; const float* be1 = (const float*)d_in[14];
    const float* g2  = (const float*)d_in[15]; const float* be2 = (const float*)d_in[16];
    float* out = (float*)d_out;

    float* x1;
    __half *a, *q, *k, *v, *h1, *wh;
    cudaGetSymbolAddress((void**)&x1, g_x1);
    cudaGetSymbolAddress((void**)&a,  g_a);
    cudaGetSymbolAddress((void**)&q,  g_q);
    cudaGetSymbolAddress((void**)&k,  g_k);
    cudaGetSymbolAddress((void**)&v,  g_v);
    cudaGetSymbolAddress((void**)&h1, g_h1);
    cudaGetSymbolAddress((void**)&wh, g_wh);

    cudaFuncSetAttribute(mm_gemm,  cudaFuncAttributeMaxDynamicSharedMemorySize, MMG_SMEM);
    cudaFuncSetAttribute(attn_mma, cudaFuncAttributeMaxDynamicSharedMemorySize, ATT_SMEM);

    const int WN = D_MODEL * D_MODEL;
    const dim3 gQKV(24, M_TOTAL / 128);
    const dim3 gGemm(8, M_TOTAL / 128);
    const dim3 gAttn(SEQ / AQ, BATCH * NHEADS);
    const dim3 gWs(WN / 4 / 256, 6);

    wconv6_kernel<<<gWs, 256>>>(Wq, Wk, Wv, Wo, W1, W2, wh);
    ln_half_kernel<<<M_TOTAL, 256>>>(src, g1, be1, a);

    mm_gemm<<<gQKV, 256, MMG_SMEM>>>(a, wh, bq, bk, bv,
                                     nullptr, nullptr, q, k, v, 0);

    attn_mma<<<gAttn, 128, ATT_SMEM>>>(q, k, v, a);

    mm_gemm<<<gGemm, 256, MMG_SMEM>>>(a, wh + 3 * WN, bo, bo, bo,
                                      src, x1, nullptr, nullptr, nullptr, 0);

    ln_half_kernel<<<M_TOTAL, 256>>>(x1, g2, be2, a);
    mm_gemm<<<gGemm, 256, MMG_SMEM>>>(a, wh + 4 * WN, b1, b1, b1,
                                      nullptr, nullptr, h1, nullptr, nullptr, 1);

    mm_gemm<<<gGemm, 256, MMG_SMEM>>>(h1, wh + 5 * WN, b2, b2, b2,
                                      x1, out, nullptr, nullptr, nullptr, 0);
}